// round 1
// baseline (speedup 1.0000x reference)
#include <cuda_runtime.h>

#define NN 50000
#define NE 800000
#define SD 128
#define NG 128
#define NC 41
#define BN_EPS 1e-5f

// ---------------- scratch (static device globals; no runtime alloc) -------
__device__ float g_x[NN * SD];
__device__ float g_y[NN * SD];
__device__ float g_h[NN * SD];
__device__ int   g_deg[NN];
__device__ int   g_rowptr[NN + 1];
__device__ int   g_cursor[NN];
__device__ int   g_csrsrc[NE];
__device__ float g_pool[NG * SD];

// ---------------- small utility kernels ----------------------------------
__global__ void k_zero_deg() {
    int i = blockIdx.x * blockDim.x + threadIdx.x;
    if (i < NN) g_deg[i] = 0;
}
__global__ void k_zero_pool() {
    int i = blockIdx.x * blockDim.x + threadIdx.x;
    if (i < NG * SD) g_pool[i] = 0.f;
}

__global__ void k_hist(const int* __restrict__ dst) {
    int e = blockIdx.x * blockDim.x + threadIdx.x;
    if (e < NE) atomicAdd(&g_deg[dst[e]], 1);
}

// single-block exclusive scan over g_deg -> g_rowptr (+ copy to g_cursor)
__global__ void k_scan() {
    __shared__ int wsum[32];
    int tid = threadIdx.x, lane = tid & 31, wid = tid >> 5;
    int base = 0;
    for (int c0 = 0; c0 < NN; c0 += 1024) {
        int i = c0 + tid;
        int v = (i < NN) ? g_deg[i] : 0;
        int s = v;
#pragma unroll
        for (int d = 1; d < 32; d <<= 1) {
            int t = __shfl_up_sync(0xffffffffu, s, d);
            if (lane >= d) s += t;
        }
        if (lane == 31) wsum[wid] = s;
        __syncthreads();
        if (wid == 0) {
            int t = wsum[lane];
#pragma unroll
            for (int d = 1; d < 32; d <<= 1) {
                int u = __shfl_up_sync(0xffffffffu, t, d);
                if (lane >= d) t += u;
            }
            wsum[lane] = t;
        }
        __syncthreads();
        int off = base + (wid ? wsum[wid - 1] : 0) + s - v;
        if (i < NN) { g_rowptr[i] = off; g_cursor[i] = off; }
        base += wsum[31];
        __syncthreads();
    }
    if (tid == 0) g_rowptr[NN] = base;
}

__global__ void k_csr(const int* __restrict__ src, const int* __restrict__ dst) {
    int e = blockIdx.x * blockDim.x + threadIdx.x;
    if (e < NE) {
        int p = atomicAdd(&g_cursor[dst[e]], 1);
        g_csrsrc[p] = src[e];
    }
}

__global__ void k_embed(const int* __restrict__ ids, const float* __restrict__ emb) {
    int t = blockIdx.x * blockDim.x + threadIdx.x;  // one float4 per thread
    if (t >= NN * 32) return;
    int n = t >> 5, q = t & 31;
    ((float4*)g_x)[n * 32 + q] = ((const float4*)emb)[(long)ids[n] * 32 + q];
}

// warp-per-node: y[i] = x[i] + sum_{j in N(i)} x[j]
__global__ void k_agg() {
    int w = (blockIdx.x * blockDim.x + threadIdx.x) >> 5;
    int lane = threadIdx.x & 31;
    if (w >= NN) return;
    const float4* x4 = (const float4*)g_x;
    float4 a = x4[w * 32 + lane];
    int e = g_rowptr[w], end = g_rowptr[w + 1];
    for (; e + 2 <= end; e += 2) {
        int j0 = g_csrsrc[e], j1 = g_csrsrc[e + 1];
        float4 v0 = x4[j0 * 32 + lane];
        float4 v1 = x4[j1 * 32 + lane];
        a.x += v0.x + v1.x; a.y += v0.y + v1.y;
        a.z += v0.z + v1.z; a.w += v0.w + v1.w;
    }
    if (e < end) {
        int j = g_csrsrc[e];
        float4 v = x4[j * 32 + lane];
        a.x += v.x; a.y += v.y; a.z += v.z; a.w += v.w;
    }
    ((float4*)g_y)[w * 32 + lane] = a;
}

// ---------------- GEMM: C[i][j] = epi( sum_k A[i][k]*W[j][k] + b[j] ) -----
// 128x128 tile per block, 256 threads, 8x8 micro-tile.
// BN_MODE 0: relu ; BN_MODE 1: bn(relu(.))
template <int BN_MODE>
__global__ void __launch_bounds__(256) k_gemm(
    const float* __restrict__ A, const float* __restrict__ W,
    const float* __restrict__ bias,
    const float* __restrict__ gamma, const float* __restrict__ beta,
    const float* __restrict__ mean, const float* __restrict__ var,
    float* __restrict__ C)
{
    __shared__ float As[16][128];
    __shared__ float Bs[16][128];
    const int tid = threadIdx.x;
    const int tx = tid & 15, ty = tid >> 4;
    const int r0 = blockIdx.x * 128;

    float acc[8][8];
#pragma unroll
    for (int i = 0; i < 8; i++)
#pragma unroll
        for (int j = 0; j < 8; j++) acc[i][j] = 0.f;

    for (int k0 = 0; k0 < 128; k0 += 16) {
#pragma unroll
        for (int i = 0; i < 2; i++) {
            int l = tid + i * 256;        // 0..511
            int row = l >> 2;             // 0..127
            int kq = (l & 3) << 2;        // 0,4,8,12
            int gr = r0 + row;
            float4 av = make_float4(0.f, 0.f, 0.f, 0.f);
            if (gr < NN) av = *(const float4*)(A + (long)gr * 128 + k0 + kq);
            As[kq + 0][row] = av.x; As[kq + 1][row] = av.y;
            As[kq + 2][row] = av.z; As[kq + 3][row] = av.w;
            float4 bv = *(const float4*)(W + (long)row * 128 + k0 + kq);
            Bs[kq + 0][row] = bv.x; Bs[kq + 1][row] = bv.y;
            Bs[kq + 2][row] = bv.z; Bs[kq + 3][row] = bv.w;
        }
        __syncthreads();
#pragma unroll
        for (int kk = 0; kk < 16; kk++) {
            float4 a0 = *(const float4*)&As[kk][ty * 8];
            float4 a1 = *(const float4*)&As[kk][ty * 8 + 4];
            float4 b0 = *(const float4*)&Bs[kk][tx * 8];
            float4 b1 = *(const float4*)&Bs[kk][tx * 8 + 4];
            float a[8] = {a0.x, a0.y, a0.z, a0.w, a1.x, a1.y, a1.z, a1.w};
            float b[8] = {b0.x, b0.y, b0.z, b0.w, b1.x, b1.y, b1.z, b1.w};
#pragma unroll
            for (int i = 0; i < 8; i++)
#pragma unroll
                for (int j = 0; j < 8; j++) acc[i][j] += a[i] * b[j];
        }
        __syncthreads();
    }

    float bj[8], scj[8], mnj[8], btj[8];
#pragma unroll
    for (int j = 0; j < 8; j++) {
        int c = tx * 8 + j;
        bj[j] = bias[c];
        if (BN_MODE) {
            scj[j] = gamma[c] * rsqrtf(var[c] + BN_EPS);
            mnj[j] = mean[c];
            btj[j] = beta[c];
        }
    }
#pragma unroll
    for (int i = 0; i < 8; i++) {
        int r = r0 + ty * 8 + i;
        if (r < NN) {
            float o[8];
#pragma unroll
            for (int j = 0; j < 8; j++) {
                float z = acc[i][j] + bj[j];
                z = fmaxf(z, 0.f);
                if (BN_MODE) z = (z - mnj[j]) * scj[j] + btj[j];
                o[j] = z;
            }
            *(float4*)(C + (long)r * 128 + tx * 8) = make_float4(o[0], o[1], o[2], o[3]);
            *(float4*)(C + (long)r * 128 + tx * 8 + 4) = make_float4(o[4], o[5], o[6], o[7]);
        }
    }
}

// ---------------- pooling (batch is sorted -> run-length accumulate) ------
#define NODES_PB 250
__global__ void k_pool(const int* __restrict__ batch) {
    int c = threadIdx.x;                 // 128 threads = columns
    int n0 = blockIdx.x * NODES_PB;
    int n1 = n0 + NODES_PB;
    if (n1 > NN) n1 = NN;
    if (n0 >= NN) return;
    float acc = 0.f;
    int cur = batch[n0];
    for (int n = n0; n < n1; n++) {
        int b = __ldg(&batch[n]);
        float v = g_x[(long)n * SD + c];
        if (b != cur) {
            atomicAdd(&g_pool[cur * SD + c], acc);
            acc = 0.f; cur = b;
        }
        acc += v;
    }
    atomicAdd(&g_pool[cur * SD + c], acc);
}

// ---------------- tiny FC head: one block per graph -----------------------
__global__ void k_fc(const float* __restrict__ fc1W, const float* __restrict__ fc1b,
                     const float* __restrict__ fc2W, const float* __restrict__ fc2b,
                     float* __restrict__ out) {
    __shared__ float p[SD];
    __shared__ float h[SD];
    int g = blockIdx.x, t = threadIdx.x;
    p[t] = g_pool[g * SD + t];
    __syncthreads();
    float s = fc1b[t];
#pragma unroll 8
    for (int k = 0; k < SD; k++) s += p[k] * fc1W[t * SD + k];
    h[t] = fmaxf(s, 0.f);
    __syncthreads();
    if (t < NC) {
        float s2 = fc2b[t];
#pragma unroll 8
        for (int k = 0; k < SD; k++) s2 += h[k] * fc2W[t * SD + k];
        out[g * NC + t] = s2;
    }
}

// ---------------- launch ---------------------------------------------------
extern "C" void kernel_launch(void* const* d_in, const int* in_sizes, int n_in,
                              void* d_out, int out_size) {
    const int*   node_ids = (const int*)d_in[0];
    const int*   edge     = (const int*)d_in[1];
    const int*   batch    = (const int*)d_in[2];
    const float* emb      = (const float*)d_in[3];
    const float* in_W1    = (const float*)d_in[4];
    const float* in_b1    = (const float*)d_in[5];
    const float* in_W2    = (const float*)d_in[6];
    const float* in_b2    = (const float*)d_in[7];
    const float* bn_gamma = (const float*)d_in[8];
    const float* bn_beta  = (const float*)d_in[9];
    const float* bn_mean  = (const float*)d_in[10];
    const float* bn_var   = (const float*)d_in[11];
    const float* out_W1   = (const float*)d_in[12];
    const float* out_b1   = (const float*)d_in[13];
    const float* out_W2   = (const float*)d_in[14];
    const float* out_b2   = (const float*)d_in[15];
    const float* fc1_W    = (const float*)d_in[16];
    const float* fc1_b    = (const float*)d_in[17];
    const float* fc2_W    = (const float*)d_in[18];
    const float* fc2_b    = (const float*)d_in[19];
    float* out = (float*)d_out;

    const int* src = edge;
    const int* dst = edge + NE;

    float *p_x, *p_y, *p_h;
    cudaGetSymbolAddress((void**)&p_x, g_x);
    cudaGetSymbolAddress((void**)&p_y, g_y);
    cudaGetSymbolAddress((void**)&p_h, g_h);

    // CSR build (once per replay)
    k_zero_deg<<<(NN + 255) / 256, 256>>>();
    k_hist<<<(NE + 255) / 256, 256>>>(dst);
    k_scan<<<1, 1024>>>();
    k_csr<<<(NE + 255) / 256, 256>>>(src, dst);

    // embedding
    k_embed<<<(NN * 32 + 255) / 256, 256>>>(node_ids, emb);

    const int GB = (NN + 127) / 128;  // 391 gemm blocks

    for (int L = 0; L < 6; L++) {
        k_agg<<<(NN * 32 + 255) / 256, 256>>>();
        const float* W1 = (L < 5) ? in_W1 : out_W1;
        const float* b1 = (L < 5) ? in_b1 : out_b1;
        const float* W2 = (L < 5) ? in_W2 : out_W2;
        const float* b2 = (L < 5) ? in_b2 : out_b2;
        k_gemm<0><<<GB, 256>>>(p_y, W1, b1, nullptr, nullptr, nullptr, nullptr, p_h);
        if (L < 5)
            k_gemm<1><<<GB, 256>>>(p_h, W2, b2, bn_gamma, bn_beta, bn_mean, bn_var, p_x);
        else
            k_gemm<0><<<GB, 256>>>(p_h, W2, b2, nullptr, nullptr, nullptr, nullptr, p_x);
    }

    // pooling + FC head
    k_zero_pool<<<(NG * SD + 255) / 256, 256>>>();
    k_pool<<<(NN + NODES_PB - 1) / NODES_PB, 128>>>(batch);
    k_fc<<<NG, 128>>>(fc1_W, fc1_b, fc2_W, fc2_b, out);
}